// round 1
// baseline (speedup 1.0000x reference)
#include <cuda_runtime.h>
#include <math.h>

#define B_   16
#define S_   512
#define DIN  768
#define HID  64
#define OUT_ 12
#define NCOL (HID * OUT_ * 2)   // 1536
#define NEGV 1e12f

// Scratch (no allocations allowed): q/k post-RoPE in (B, OUT, S, HID) layout.
__device__ float g_q[B_ * OUT_ * S_ * HID];
__device__ float g_k[B_ * OUT_ * S_ * HID];
__device__ float g_sin[S_ * 32];
__device__ float g_cos[S_ * 32];

// ---------------------------------------------------------------------------
// k0: RoPE angle table. ang(s,j) = s * 10000^(-j/32), j in [0,32)
// ---------------------------------------------------------------------------
__global__ void rope_table_kernel() {
    int i = blockIdx.x * blockDim.x + threadIdx.x;
    if (i >= S_ * 32) return;
    int s = i >> 5, j = i & 31;
    // inv_freq = 10000^(-2j/64) = exp(-j * ln(10000)/32)
    float invf = expf(-(float)j * 0.28782313662425586f);
    float ang = (float)s * invf;
    g_sin[i] = sinf(ang);
    g_cos[i] = cosf(ang);
}

// ---------------------------------------------------------------------------
// k1: proj = x @ W + b, fused interleaved RoPE, scatter to g_q / g_k.
// M=8192, N=1536, K=768. Tile 64x64, BK=16, 256 threads, 4x4 microtile.
// ---------------------------------------------------------------------------
#define BM 64
#define BN 64
#define BK 16

__global__ __launch_bounds__(256)
void proj_rope_kernel(const float* __restrict__ X,
                      const float* __restrict__ W,
                      const float* __restrict__ bias) {
    __shared__ float As[BK][BM + 4];   // transposed A tile, padded
    __shared__ float Bs[BK][BN];

    const int tid = threadIdx.x;
    const int tx = tid & 15;           // column group
    const int ty = tid >> 4;           // row group
    const int bm = blockIdx.y * BM;
    const int bn = blockIdx.x * BN;

    // global load mapping
    const int arow = tid >> 2;               // 0..63
    const int acol = (tid & 3) * 4;          // 0,4,8,12
    const int brow = tid >> 4;               // 0..15
    const int bcol = (tid & 15) * 4;         // 0..60

    const float* Aptr = X + (size_t)(bm + arow) * DIN + acol;
    const float* Bptr = W + (size_t)brow * NCOL + bn + bcol;

    float acc[4][4] = {};

    for (int k0 = 0; k0 < DIN; k0 += BK) {
        float4 a  = *(const float4*)(Aptr + k0);
        float4 bv = *(const float4*)(Bptr + (size_t)k0 * NCOL);
        As[acol + 0][arow] = a.x;
        As[acol + 1][arow] = a.y;
        As[acol + 2][arow] = a.z;
        As[acol + 3][arow] = a.w;
        *(float4*)&Bs[brow][bcol] = bv;
        __syncthreads();

#pragma unroll
        for (int k = 0; k < BK; k++) {
            float4 af = *(const float4*)&As[k][ty * 4];
            float4 bf = *(const float4*)&Bs[k][tx * 4];
            float av[4] = {af.x, af.y, af.z, af.w};
            float bw[4] = {bf.x, bf.y, bf.z, bf.w};
#pragma unroll
            for (int i = 0; i < 4; i++)
#pragma unroll
                for (int j = 0; j < 4; j++)
                    acc[i][j] = fmaf(av[i], bw[j], acc[i][j]);
        }
        __syncthreads();
    }

    // Epilogue: bias + interleaved RoPE, scatter to q/k scratch.
    // col c -> head o = c/128, inner = c%128; inner<64 => q[d=inner] else k[d=inner-64]
    // RoPE pairs (d even, d+1):
    //   out[d]   = w[d]*cos[d%32]     - w[d+1]*sin[d%32]
    //   out[d+1] = w[d+1]*cos[(d+1)%32] + w[d]*sin[(d+1)%32]
#pragma unroll
    for (int i = 0; i < 4; i++) {
        int m = bm + ty * 4 + i;
        int b = m >> 9;            // /512
        int s = m & 511;
        const float* sintab = g_sin + s * 32;
        const float* costab = g_cos + s * 32;
#pragma unroll
        for (int j = 0; j < 4; j += 2) {
            int c0 = bn + tx * 4 + j;          // even
            float v0 = acc[i][j]     + bias[c0];
            float v1 = acc[i][j + 1] + bias[c0 + 1];
            int o     = c0 >> 7;
            int inner = c0 & 127;
            int d     = inner & 63;            // even
            float ce = costab[d & 31];
            float se = sintab[d & 31];
            float co = costab[(d + 1) & 31];
            float so = sintab[(d + 1) & 31];
            float r0 = v0 * ce - v1 * se;
            float r1 = v1 * co + v0 * so;
            float* dst = ((inner >= 64) ? g_k : g_q)
                         + (((size_t)(b * OUT_ + o) * S_ + s) * HID + d);
            dst[0] = r0;
            dst[1] = r1;
        }
    }
}

// ---------------------------------------------------------------------------
// k2: logits[bh, m, n] = (sum_d q[bh,m,d]*k[bh,n,d]) with mask/causal/scale.
// Per (b,h): 512x512x64. Tile 64x64, full K=64 in smem, 256 threads, 4x4.
// ---------------------------------------------------------------------------
__global__ __launch_bounds__(256)
void logits_kernel(const float* __restrict__ mask, float* __restrict__ out) {
    __shared__ float Qs[HID][64 + 4];
    __shared__ float Ks[HID][64 + 4];

    const int tid = threadIdx.x;
    const int tx = tid & 15;
    const int ty = tid >> 4;
    const int bh = blockIdx.z;                // b*12 + h
    const int m0 = blockIdx.y * 64;
    const int n0 = blockIdx.x * 64;
    const int b  = bh / OUT_;

    const float* Qg = g_q + (size_t)bh * S_ * HID;
    const float* Kg = g_k + (size_t)bh * S_ * HID;

    // load 64x64 q and k tiles, transposed into smem [d][row]
    const int lrow  = tid >> 2;               // 0..63
    const int dbase = (tid & 3) * 16;         // 0,16,32,48
#pragma unroll
    for (int u = 0; u < 4; u++) {
        int dd = dbase + u * 4;
        float4 q  = *(const float4*)(Qg + (size_t)(m0 + lrow) * HID + dd);
        float4 kk = *(const float4*)(Kg + (size_t)(n0 + lrow) * HID + dd);
        Qs[dd + 0][lrow] = q.x;  Qs[dd + 1][lrow] = q.y;
        Qs[dd + 2][lrow] = q.z;  Qs[dd + 3][lrow] = q.w;
        Ks[dd + 0][lrow] = kk.x; Ks[dd + 1][lrow] = kk.y;
        Ks[dd + 2][lrow] = kk.z; Ks[dd + 3][lrow] = kk.w;
    }
    __syncthreads();

    float acc[4][4] = {};
#pragma unroll
    for (int d = 0; d < HID; d++) {
        float4 qf = *(const float4*)&Qs[d][ty * 4];
        float4 kf = *(const float4*)&Ks[d][tx * 4];
        float qv[4] = {qf.x, qf.y, qf.z, qf.w};
        float kv[4] = {kf.x, kf.y, kf.z, kf.w};
#pragma unroll
        for (int i = 0; i < 4; i++)
#pragma unroll
            for (int j = 0; j < 4; j++)
                acc[i][j] = fmaf(qv[i], kv[j], acc[i][j]);
    }

    // epilogue: mask, strict-lower-triangular NEG, scale 1/8
    float pad[4], padneg[4];
#pragma unroll
    for (int j = 0; j < 4; j++) {
        int n = n0 + tx * 4 + j;
        pad[j] = mask[b * S_ + n];
        padneg[j] = (1.0f - pad[j]) * NEGV;
    }
#pragma unroll
    for (int i = 0; i < 4; i++) {
        int m = m0 + ty * 4 + i;
        float4 res;
        float* rp = (float*)&res;
#pragma unroll
        for (int j = 0; j < 4; j++) {
            int n = n0 + tx * 4 + j;
            float v = acc[i][j] * pad[j] - padneg[j];
            if (m > n) v -= NEGV;
            rp[j] = v * 0.125f;
        }
        *(float4*)(out + ((size_t)bh * S_ + m) * S_ + n0 + tx * 4) = res;
    }
}

// ---------------------------------------------------------------------------
extern "C" void kernel_launch(void* const* d_in, const int* in_sizes, int n_in,
                              void* d_out, int out_size) {
    const float* x    = (const float*)d_in[0];   // (16,512,768)
    const float* mask = (const float*)d_in[1];   // (16,512)
    const float* W    = (const float*)d_in[2];   // (768,1536)
    const float* bias = (const float*)d_in[3];   // (1536,)
    float* out = (float*)d_out;                  // (16,12,512,512)

    rope_table_kernel<<<(S_ * 32 + 255) / 256, 256>>>();

    dim3 g1(NCOL / BN, (B_ * S_) / BM);          // (24, 128)
    proj_rope_kernel<<<g1, 256>>>(x, W, bias);

    dim3 g2(S_ / 64, S_ / 64, B_ * OUT_);        // (8, 8, 192)
    logits_kernel<<<g2, 256>>>(mask, out);
}

// round 2
// speedup vs baseline: 3.8885x; 3.8885x over previous
#include <cuda_runtime.h>
#include <cuda_bf16.h>
#include <math.h>

#define B_   16
#define S_   512
#define DIN  768
#define HID  64
#define OUT_ 12
#define NCOL 1536
#define BH   (B_ * OUT_)
#define NEGV 1e12f

// Scratch (no allocation allowed) — bf16 operands + RoPE tables.
__device__ __align__(16) __nv_bfloat16 g_xb[B_ * S_ * DIN];
__device__ __align__(16) __nv_bfloat16 g_wt[NCOL * DIN];        // W transposed: [n][k]
__device__ __align__(16) __nv_bfloat16 g_qb[BH * S_ * HID];
__device__ __align__(16) __nv_bfloat16 g_kb[BH * S_ * HID];
__device__ float g_sin[S_ * 32];
__device__ float g_cos[S_ * 32];

// ---------------------------------------------------------------------------
__device__ __forceinline__ void mma_bf16(float acc[4], const unsigned a[4],
                                         const unsigned b[2]) {
    asm volatile(
        "mma.sync.aligned.m16n8k16.row.col.f32.bf16.bf16.f32 "
        "{%0,%1,%2,%3}, {%4,%5,%6,%7}, {%8,%9}, {%0,%1,%2,%3};\n"
        : "+f"(acc[0]), "+f"(acc[1]), "+f"(acc[2]), "+f"(acc[3])
        : "r"(a[0]), "r"(a[1]), "r"(a[2]), "r"(a[3]), "r"(b[0]), "r"(b[1]));
}

// ---------------------------------------------------------------------------
// k0: RoPE angle tables
// ---------------------------------------------------------------------------
__global__ void rope_table_kernel() {
    int i = blockIdx.x * blockDim.x + threadIdx.x;
    if (i >= S_ * 32) return;
    int s = i >> 5, j = i & 31;
    float invf = expf(-(float)j * 0.28782313662425586f); // ln(10000)/32
    float ang = (float)s * invf;
    g_sin[i] = sinf(ang);
    g_cos[i] = cosf(ang);
}

// ---------------------------------------------------------------------------
// k1: x fp32 -> bf16
// ---------------------------------------------------------------------------
__global__ void cvt_x_kernel(const float4* __restrict__ x) {
    int i = blockIdx.x * blockDim.x + threadIdx.x; // 1572864 total
    float4 v = x[i];
    __nv_bfloat162* dst = (__nv_bfloat162*)g_xb;
    dst[i * 2 + 0] = __floats2bfloat162_rn(v.x, v.y);
    dst[i * 2 + 1] = __floats2bfloat162_rn(v.z, v.w);
}

// ---------------------------------------------------------------------------
// k2: W (K x N, fp32) -> g_wt (N x K, bf16) tiled transpose
// ---------------------------------------------------------------------------
__global__ void cvt_wt_kernel(const float* __restrict__ W) {
    __shared__ float tile[32][33];
    int nb = blockIdx.x * 32, kb = blockIdx.y * 32;
    int tx = threadIdx.x, ty = threadIdx.y; // 32 x 8
#pragma unroll
    for (int u = 0; u < 4; u++)
        tile[ty + u * 8][tx] = W[(size_t)(kb + ty + u * 8) * NCOL + nb + tx];
    __syncthreads();
#pragma unroll
    for (int u = 0; u < 4; u++)
        g_wt[(size_t)(nb + ty + u * 8) * DIN + kb + tx] =
            __float2bfloat16(tile[tx][ty + u * 8]);
}

// ---------------------------------------------------------------------------
// k3: GEMM1  proj = x @ W + b  (M=8192, N=1536, K=768), fused RoPE epilogue.
// Block 128x128, BK=32, 8 warps (2x4), warp tile 64x32, mma m16n8k16 bf16.
// ---------------------------------------------------------------------------
#define G1_BK 32
#define G1_LD (G1_BK + 8) // 40 bf16 stride: conflict-free frag LDS

__global__ __launch_bounds__(256)
void gemm1_kernel(const float* __restrict__ bias) {
    __shared__ __nv_bfloat16 As[128][G1_LD];
    __shared__ __nv_bfloat16 Bs[128][G1_LD];

    const int tid = threadIdx.x;
    const int lane = tid & 31;
    const int warp = tid >> 5;
    const int wm = (warp & 1) * 64;
    const int wn = (warp >> 1) * 32;
    const int g = lane >> 2;
    const int t = lane & 3;

    const int bm = blockIdx.y * 128;
    const int bn = blockIdx.x * 128;

    const int lrow = tid >> 2;          // 0..63
    const int lcb  = (tid & 3) * 8;     // 0,8,16,24 (bf16 cols)

    const __nv_bfloat16* Ag = g_xb + (size_t)(bm + lrow) * DIN + lcb;
    const __nv_bfloat16* Bg = g_wt + (size_t)(bn + lrow) * DIN + lcb;

    float acc[4][4][4] = {};

    uint4 ra0 = *(const uint4*)(Ag);
    uint4 ra1 = *(const uint4*)(Ag + (size_t)64 * DIN);
    uint4 rb0 = *(const uint4*)(Bg);
    uint4 rb1 = *(const uint4*)(Bg + (size_t)64 * DIN);

    for (int k0 = 0; k0 < DIN; k0 += G1_BK) {
        *(uint4*)&As[lrow][lcb]      = ra0;
        *(uint4*)&As[lrow + 64][lcb] = ra1;
        *(uint4*)&Bs[lrow][lcb]      = rb0;
        *(uint4*)&Bs[lrow + 64][lcb] = rb1;
        __syncthreads();

        if (k0 + G1_BK < DIN) {
            ra0 = *(const uint4*)(Ag + k0 + G1_BK);
            ra1 = *(const uint4*)(Ag + (size_t)64 * DIN + k0 + G1_BK);
            rb0 = *(const uint4*)(Bg + k0 + G1_BK);
            rb1 = *(const uint4*)(Bg + (size_t)64 * DIN + k0 + G1_BK);
        }

#pragma unroll
        for (int ks = 0; ks < 2; ks++) {
            const int kb = ks * 16;
            unsigned afr[4][4], bfr[4][2];
#pragma unroll
            for (int im = 0; im < 4; im++) {
                int r = wm + im * 16 + g;
                afr[im][0] = *(const unsigned*)&As[r][kb + 2 * t];
                afr[im][1] = *(const unsigned*)&As[r + 8][kb + 2 * t];
                afr[im][2] = *(const unsigned*)&As[r][kb + 8 + 2 * t];
                afr[im][3] = *(const unsigned*)&As[r + 8][kb + 8 + 2 * t];
            }
#pragma unroll
            for (int jn = 0; jn < 4; jn++) {
                int r = wn + jn * 8 + g;
                bfr[jn][0] = *(const unsigned*)&Bs[r][kb + 2 * t];
                bfr[jn][1] = *(const unsigned*)&Bs[r][kb + 8 + 2 * t];
            }
#pragma unroll
            for (int im = 0; im < 4; im++)
#pragma unroll
                for (int jn = 0; jn < 4; jn++)
                    mma_bf16(acc[im][jn], afr[im], bfr[jn]);
        }
        __syncthreads();
    }

    // Epilogue: bias + interleaved RoPE -> bf16 q/k scratch (B,OUT,S,HID)
#pragma unroll
    for (int im = 0; im < 4; im++) {
#pragma unroll
        for (int half = 0; half < 2; half++) {
            int m = bm + wm + im * 16 + g + half * 8;
            int b = m >> 9, s = m & 511;
            const float* st = g_sin + s * 32;
            const float* ct = g_cos + s * 32;
#pragma unroll
            for (int jn = 0; jn < 4; jn++) {
                int c = bn + wn + jn * 8 + 2 * t;   // even
                float v0 = acc[im][jn][half * 2 + 0] + bias[c];
                float v1 = acc[im][jn][half * 2 + 1] + bias[c + 1];
                int o = c >> 7, inner = c & 127, d = inner & 63;
                float ce = ct[d & 31],       se = st[d & 31];
                float co = ct[(d + 1) & 31], so = st[(d + 1) & 31];
                float r0 = v0 * ce - v1 * se;
                float r1 = v1 * co + v0 * so;
                __nv_bfloat16* dst = ((inner >= 64) ? g_kb : g_qb) +
                    (((size_t)(b * OUT_ + o) * S_ + s) * HID + d);
                *(__nv_bfloat162*)dst = __floats2bfloat162_rn(r0, r1);
            }
        }
    }
}

// ---------------------------------------------------------------------------
// k4: logits = q @ k^T per (b,h), mask/causal/scale epilogue.
// Block 128x128, K=64 fully resident, 8 warps (2x4), warp 64x32.
// ---------------------------------------------------------------------------
#define G2_LD (HID + 8) // 72 bf16 stride: conflict-free

__global__ __launch_bounds__(256)
void gemm2_kernel(const float* __restrict__ mask, float* __restrict__ out) {
    __shared__ __nv_bfloat16 Qs[128][G2_LD];
    __shared__ __nv_bfloat16 Ks[128][G2_LD];

    const int tid = threadIdx.x;
    const int lane = tid & 31;
    const int warp = tid >> 5;
    const int wm = (warp & 1) * 64;
    const int wn = (warp >> 1) * 32;
    const int g = lane >> 2;
    const int t = lane & 3;

    const int bh = blockIdx.z;
    const int m0b = blockIdx.y * 128;
    const int n0b = blockIdx.x * 128;
    const int b = bh / OUT_;

    const __nv_bfloat16* Qg = g_qb + (size_t)bh * S_ * HID;
    const __nv_bfloat16* Kg = g_kb + (size_t)bh * S_ * HID;

#pragma unroll
    for (int u = 0; u < 4; u++) {
        int vv = tid + u * 256;
        int row = vv >> 3, cb = (vv & 7) * 8;
        *(uint4*)&Qs[row][cb] = *(const uint4*)(Qg + (size_t)(m0b + row) * HID + cb);
        *(uint4*)&Ks[row][cb] = *(const uint4*)(Kg + (size_t)(n0b + row) * HID + cb);
    }
    __syncthreads();

    float acc[4][4][4] = {};
#pragma unroll
    for (int ks = 0; ks < 4; ks++) {
        const int kb = ks * 16;
        unsigned afr[4][4], bfr[4][2];
#pragma unroll
        for (int im = 0; im < 4; im++) {
            int r = wm + im * 16 + g;
            afr[im][0] = *(const unsigned*)&Qs[r][kb + 2 * t];
            afr[im][1] = *(const unsigned*)&Qs[r + 8][kb + 2 * t];
            afr[im][2] = *(const unsigned*)&Qs[r][kb + 8 + 2 * t];
            afr[im][3] = *(const unsigned*)&Qs[r + 8][kb + 8 + 2 * t];
        }
#pragma unroll
        for (int jn = 0; jn < 4; jn++) {
            int r = wn + jn * 8 + g;
            bfr[jn][0] = *(const unsigned*)&Ks[r][kb + 2 * t];
            bfr[jn][1] = *(const unsigned*)&Ks[r][kb + 8 + 2 * t];
        }
#pragma unroll
        for (int im = 0; im < 4; im++)
#pragma unroll
            for (int jn = 0; jn < 4; jn++)
                mma_bf16(acc[im][jn], afr[im], bfr[jn]);
    }

    // epilogue
    float padv[4][2], png[4][2];
#pragma unroll
    for (int jn = 0; jn < 4; jn++) {
        int n = n0b + wn + jn * 8 + 2 * t;
        float p0 = mask[b * S_ + n], p1 = mask[b * S_ + n + 1];
        padv[jn][0] = p0; padv[jn][1] = p1;
        png[jn][0] = (1.0f - p0) * NEGV;
        png[jn][1] = (1.0f - p1) * NEGV;
    }
#pragma unroll
    for (int im = 0; im < 4; im++) {
#pragma unroll
        for (int half = 0; half < 2; half++) {
            int m = m0b + wm + im * 16 + g + half * 8;
            float* orow = out + ((size_t)bh * S_ + m) * S_;
#pragma unroll
            for (int jn = 0; jn < 4; jn++) {
                int n = n0b + wn + jn * 8 + 2 * t;
                float v0 = acc[im][jn][half * 2 + 0] * padv[jn][0] - png[jn][0];
                float v1 = acc[im][jn][half * 2 + 1] * padv[jn][1] - png[jn][1];
                if (m > n)     v0 -= NEGV;
                if (m > n + 1) v1 -= NEGV;
                *(float2*)(orow + n) = make_float2(v0 * 0.125f, v1 * 0.125f);
            }
        }
    }
}

// ---------------------------------------------------------------------------
extern "C" void kernel_launch(void* const* d_in, const int* in_sizes, int n_in,
                              void* d_out, int out_size) {
    const float* x    = (const float*)d_in[0];
    const float* mask = (const float*)d_in[1];
    const float* W    = (const float*)d_in[2];
    const float* bias = (const float*)d_in[3];
    float* out = (float*)d_out;

    rope_table_kernel<<<(S_ * 32 + 255) / 256, 256>>>();
    cvt_x_kernel<<<(B_ * S_ * DIN / 4 + 255) / 256, 256>>>((const float4*)x);
    cvt_wt_kernel<<<dim3(NCOL / 32, DIN / 32), dim3(32, 8)>>>(W);

    dim3 g1(NCOL / 128, (B_ * S_) / 128);       // (12, 64)
    gemm1_kernel<<<g1, 256>>>(bias);

    dim3 g2(S_ / 128, S_ / 128, BH);            // (4, 4, 192)
    gemm2_kernel<<<g2, 256>>>(mask, out);
}

// round 3
// speedup vs baseline: 4.2134x; 1.0836x over previous
#include <cuda_runtime.h>
#include <cuda_bf16.h>
#include <math.h>

#define B_   16
#define S_   512
#define DIN  768
#define HID  64
#define OUT_ 12
#define NCOL 1536
#define BH   (B_ * OUT_)
#define NEGV 1e12f

// Scratch (no allocation allowed) — bf16 operands + RoPE tables.
__device__ __align__(16) __nv_bfloat16 g_xb[B_ * S_ * DIN];
__device__ __align__(16) __nv_bfloat16 g_wt[NCOL * DIN];   // W transposed: [n][k]
__device__ __align__(16) __nv_bfloat16 g_qb[BH * S_ * HID];
__device__ __align__(16) __nv_bfloat16 g_kb[BH * S_ * HID];
__device__ float g_sin[S_ * 32];
__device__ float g_cos[S_ * 32];

// ---------------------------------------------------------------------------
__device__ __forceinline__ void mma_bf16(float acc[4], const unsigned a[4],
                                         const unsigned b[2]) {
    asm volatile(
        "mma.sync.aligned.m16n8k16.row.col.f32.bf16.bf16.f32 "
        "{%0,%1,%2,%3}, {%4,%5,%6,%7}, {%8,%9}, {%0,%1,%2,%3};\n"
        : "+f"(acc[0]), "+f"(acc[1]), "+f"(acc[2]), "+f"(acc[3])
        : "r"(a[0]), "r"(a[1]), "r"(a[2]), "r"(a[3]), "r"(b[0]), "r"(b[1]));
}

__device__ __forceinline__ unsigned sptr(const void* p) {
    return (unsigned)__cvta_generic_to_shared(p);
}

__device__ __forceinline__ void ldsm_x4(unsigned r[4], unsigned addr) {
    asm volatile("ldmatrix.sync.aligned.m8n8.x4.shared.b16 {%0,%1,%2,%3}, [%4];"
                 : "=r"(r[0]), "=r"(r[1]), "=r"(r[2]), "=r"(r[3]) : "r"(addr));
}

#define CP_A16(saddr, gptr) \
    asm volatile("cp.async.cg.shared.global [%0], [%1], 16;\n" :: "r"(saddr), "l"(gptr))
#define CP_COMMIT() asm volatile("cp.async.commit_group;\n")
#define CP_WAIT0()  asm volatile("cp.async.wait_group 0;\n")

// ---------------------------------------------------------------------------
// k0: RoPE tables
// ---------------------------------------------------------------------------
__global__ void rope_table_kernel() {
    int i = blockIdx.x * blockDim.x + threadIdx.x;
    if (i >= S_ * 32) return;
    int s = i >> 5, j = i & 31;
    float invf = __expf(-(float)j * 0.28782313662425586f); // ln(10000)/32
    float ang = (float)s * invf;
    float sv, cv;
    sincosf(ang, &sv, &cv);
    g_sin[i] = sv;
    g_cos[i] = cv;
}

// ---------------------------------------------------------------------------
// k1: x fp32 -> bf16 (8 floats / thread, one uint4 store)
// ---------------------------------------------------------------------------
__global__ void cvt_x_kernel(const float4* __restrict__ x) {
    int i = blockIdx.x * blockDim.x + threadIdx.x; // 786432 threads
    float4 a = x[2 * i], b = x[2 * i + 1];
    union { __nv_bfloat162 h[4]; uint4 u; } o;
    o.h[0] = __floats2bfloat162_rn(a.x, a.y);
    o.h[1] = __floats2bfloat162_rn(a.z, a.w);
    o.h[2] = __floats2bfloat162_rn(b.x, b.y);
    o.h[3] = __floats2bfloat162_rn(b.z, b.w);
    ((uint4*)g_xb)[i] = o.u;
}

// ---------------------------------------------------------------------------
// k2: W (K x N fp32) -> g_wt (N x K bf16) tiled transpose
// ---------------------------------------------------------------------------
__global__ void cvt_wt_kernel(const float* __restrict__ W) {
    __shared__ float tile[32][33];
    int nb = blockIdx.x * 32, kb = blockIdx.y * 32;
    int tx = threadIdx.x, ty = threadIdx.y; // 32 x 8
#pragma unroll
    for (int u = 0; u < 4; u++)
        tile[ty + u * 8][tx] = W[(size_t)(kb + ty + u * 8) * NCOL + nb + tx];
    __syncthreads();
#pragma unroll
    for (int u = 0; u < 4; u++)
        g_wt[(size_t)(nb + ty + u * 8) * DIN + kb + tx] =
            __float2bfloat16(tile[tx][ty + u * 8]);
}

// ---------------------------------------------------------------------------
// k3: GEMM1  proj = x @ W + b  (8192 x 1536 x 768), ldmatrix + cp.async
// Block 128x128, BK=32, double-buffered smem, 8 warps (2x4), warp 64x32.
// ---------------------------------------------------------------------------
#define G1_LD 40          // bf16 stride; 80B: ldmatrix conflict-free
#define G1_ITERS (DIN / 32)

__global__ __launch_bounds__(256, 2)
void gemm1_kernel(const float* __restrict__ bias) {
    __shared__ __nv_bfloat16 sA[2][128][G1_LD];
    __shared__ __nv_bfloat16 sB[2][128][G1_LD];

    const int tid  = threadIdx.x;
    const int lane = tid & 31;
    const int warp = tid >> 5;
    const int wm = (warp & 1) * 64;
    const int wn = (warp >> 1) * 32;
    const int g = lane >> 2;
    const int t = lane & 3;

    const int bm = blockIdx.y * 128;
    const int bn = blockIdx.x * 128;

    // cp.async mapping: thread covers rows (tid>>2) and (tid>>2)+64, seg (tid&3)*8
    const int crow = tid >> 2;
    const int cseg = (tid & 3) * 8;
    const __nv_bfloat16* Ag = g_xb + (size_t)(bm + crow) * DIN + cseg;
    const __nv_bfloat16* Bg = g_wt + (size_t)(bn + crow) * DIN + cseg;

    // ldmatrix address components (shared per thread)
    const int lrow = lane & 15;
    const int lcol = (lane >> 4) << 3;

    float acc[4][4][4] = {};

#define G1_ISSUE(it)                                                          \
    do {                                                                      \
        int _k0 = (it) * 32, _b = (it) & 1;                                   \
        CP_A16(sptr(&sA[_b][crow][cseg]),      Ag + _k0);                     \
        CP_A16(sptr(&sA[_b][crow + 64][cseg]), Ag + (size_t)64 * DIN + _k0);  \
        CP_A16(sptr(&sB[_b][crow][cseg]),      Bg + _k0);                     \
        CP_A16(sptr(&sB[_b][crow + 64][cseg]), Bg + (size_t)64 * DIN + _k0);  \
        CP_COMMIT();                                                          \
    } while (0)

    G1_ISSUE(0);

    for (int it = 0; it < G1_ITERS; it++) {
        CP_WAIT0();
        __syncthreads();
        if (it + 1 < G1_ITERS) G1_ISSUE(it + 1);

        const int buf = it & 1;
#pragma unroll
        for (int ks = 0; ks < 2; ks++) {
            const int kb = ks * 16;
            unsigned afr[4][4], bfr[4][2];
#pragma unroll
            for (int im = 0; im < 4; im++)
                ldsm_x4(afr[im], sptr(&sA[buf][wm + im * 16 + lrow][kb + lcol]));
#pragma unroll
            for (int p = 0; p < 2; p++) {
                unsigned tmp[4];
                ldsm_x4(tmp, sptr(&sB[buf][wn + p * 16 + lrow][kb + lcol]));
                bfr[2 * p][0]     = tmp[0];
                bfr[2 * p + 1][0] = tmp[1];
                bfr[2 * p][1]     = tmp[2];
                bfr[2 * p + 1][1] = tmp[3];
            }
#pragma unroll
            for (int im = 0; im < 4; im++)
#pragma unroll
                for (int jn = 0; jn < 4; jn++)
                    mma_bf16(acc[im][jn], afr[im], bfr[jn]);
        }
        __syncthreads();
    }

    // Epilogue: bias + interleaved RoPE -> bf16 q/k scratch (B,OUT,S,HID)
#pragma unroll
    for (int im = 0; im < 4; im++) {
#pragma unroll
        for (int half = 0; half < 2; half++) {
            int m = bm + wm + im * 16 + g + half * 8;
            int b = m >> 9, s = m & 511;
            const float* st = g_sin + s * 32;
            const float* ct = g_cos + s * 32;
#pragma unroll
            for (int jn = 0; jn < 4; jn++) {
                int c = bn + wn + jn * 8 + 2 * t;   // even
                float v0 = acc[im][jn][half * 2 + 0] + bias[c];
                float v1 = acc[im][jn][half * 2 + 1] + bias[c + 1];
                int o = c >> 7, inner = c & 127, d = inner & 63;
                float ce = ct[d & 31],       se = st[d & 31];
                float co = ct[(d + 1) & 31], so = st[(d + 1) & 31];
                float r0 = v0 * ce - v1 * se;
                float r1 = v1 * co + v0 * so;
                __nv_bfloat16* dst = ((inner >= 64) ? g_kb : g_qb) +
                    (((size_t)(b * OUT_ + o) * S_ + s) * HID + d);
                *(__nv_bfloat162*)dst = __floats2bfloat162_rn(r0, r1);
            }
        }
    }
}

// ---------------------------------------------------------------------------
// k4: logits = q @ k^T per (b,h); ldmatrix; mask/causal/scale epilogue.
// Block 128x128, full K=64 in smem, 8 warps (2x4), warp 64x32.
// ---------------------------------------------------------------------------
#define G2_LD (HID + 8) // 72 bf16 stride, 144B: ldmatrix conflict-free

__global__ __launch_bounds__(256, 2)
void gemm2_kernel(const float* __restrict__ mask, float* __restrict__ out) {
    __shared__ __nv_bfloat16 Qs[128][G2_LD];
    __shared__ __nv_bfloat16 Ks[128][G2_LD];

    const int tid  = threadIdx.x;
    const int lane = tid & 31;
    const int warp = tid >> 5;
    const int wm = (warp & 1) * 64;
    const int wn = (warp >> 1) * 32;
    const int g = lane >> 2;
    const int t = lane & 3;

    const int bh  = blockIdx.z;
    const int m0b = blockIdx.y * 128;
    const int n0b = blockIdx.x * 128;
    const int b   = bh / OUT_;

    const __nv_bfloat16* Qg = g_qb + (size_t)bh * S_ * HID;
    const __nv_bfloat16* Kg = g_kb + (size_t)bh * S_ * HID;

#pragma unroll
    for (int u = 0; u < 4; u++) {
        int vv = tid + u * 256;
        int row = vv >> 3, cb = (vv & 7) * 8;
        *(uint4*)&Qs[row][cb] = *(const uint4*)(Qg + (size_t)(m0b + row) * HID + cb);
        *(uint4*)&Ks[row][cb] = *(const uint4*)(Kg + (size_t)(n0b + row) * HID + cb);
    }
    __syncthreads();

    const int lrow = lane & 15;
    const int lcol = (lane >> 4) << 3;

    float acc[4][4][4] = {};
#pragma unroll
    for (int ks = 0; ks < 4; ks++) {
        const int kb = ks * 16;
        unsigned afr[4][4], bfr[4][2];
#pragma unroll
        for (int im = 0; im < 4; im++)
            ldsm_x4(afr[im], sptr(&Qs[wm + im * 16 + lrow][kb + lcol]));
#pragma unroll
        for (int p = 0; p < 2; p++) {
            unsigned tmp[4];
            ldsm_x4(tmp, sptr(&Ks[wn + p * 16 + lrow][kb + lcol]));
            bfr[2 * p][0]     = tmp[0];
            bfr[2 * p + 1][0] = tmp[1];
            bfr[2 * p][1]     = tmp[2];
            bfr[2 * p + 1][1] = tmp[3];
        }
#pragma unroll
        for (int im = 0; im < 4; im++)
#pragma unroll
            for (int jn = 0; jn < 4; jn++)
                mma_bf16(acc[im][jn], afr[im], bfr[jn]);
    }

    // epilogue: mask, strict-lower causal, scale 1/8
    float padv[4][2], png[4][2];
#pragma unroll
    for (int jn = 0; jn < 4; jn++) {
        int n = n0b + wn + jn * 8 + 2 * t;
        float p0 = mask[b * S_ + n], p1 = mask[b * S_ + n + 1];
        padv[jn][0] = p0; padv[jn][1] = p1;
        png[jn][0] = (1.0f - p0) * NEGV;
        png[jn][1] = (1.0f - p1) * NEGV;
    }
#pragma unroll
    for (int im = 0; im < 4; im++) {
#pragma unroll
        for (int half = 0; half < 2; half++) {
            int m = m0b + wm + im * 16 + g + half * 8;
            float* orow = out + ((size_t)bh * S_ + m) * S_;
#pragma unroll
            for (int jn = 0; jn < 4; jn++) {
                int n = n0b + wn + jn * 8 + 2 * t;
                float v0 = acc[im][jn][half * 2 + 0] * padv[jn][0] - png[jn][0];
                float v1 = acc[im][jn][half * 2 + 1] * padv[jn][1] - png[jn][1];
                if (m > n)     v0 -= NEGV;
                if (m > n + 1) v1 -= NEGV;
                *(float2*)(orow + n) = make_float2(v0 * 0.125f, v1 * 0.125f);
            }
        }
    }
}

// ---------------------------------------------------------------------------
extern "C" void kernel_launch(void* const* d_in, const int* in_sizes, int n_in,
                              void* d_out, int out_size) {
    const float* x    = (const float*)d_in[0];
    const float* mask = (const float*)d_in[1];
    const float* W    = (const float*)d_in[2];
    const float* bias = (const float*)d_in[3];
    float* out = (float*)d_out;

    rope_table_kernel<<<(S_ * 32 + 255) / 256, 256>>>();
    cvt_x_kernel<<<(B_ * S_ * DIN / 8 + 255) / 256, 256>>>((const float4*)x);
    cvt_wt_kernel<<<dim3(NCOL / 32, DIN / 32), dim3(32, 8)>>>(W);

    dim3 g1(NCOL / 128, (B_ * S_) / 128);       // (12, 64)
    gemm1_kernel<<<g1, 256>>>(bias);

    dim3 g2(S_ / 128, S_ / 128, BH);            // (4, 4, 192)
    gemm2_kernel<<<g2, 256>>>(mask, out);
}

// round 5
// speedup vs baseline: 5.1671x; 1.2264x over previous
#include <cuda_runtime.h>
#include <cuda_bf16.h>
#include <math.h>
#include <stdint.h>

#define B_   16
#define S_   512
#define DIN  768
#define HID  64
#define OUT_ 12
#define NCOL 1536
#define BH   (B_ * OUT_)
#define NEGV 1e12f

// Scratch (no allocation allowed)
__device__ __align__(16) __nv_bfloat16 g_xb[B_ * S_ * DIN];
__device__ __align__(16) __nv_bfloat16 g_wt[NCOL * DIN];   // W transposed [n][k]
__device__ __align__(16) __nv_bfloat16 g_qb[BH * S_ * HID];
__device__ __align__(16) __nv_bfloat16 g_kb[BH * S_ * HID];
__device__ float g_sin[S_ * 32];
__device__ float g_cos[S_ * 32];

// ---------------------------------------------------------------------------
__device__ __forceinline__ uint32_t cvta_s(const void* p) {
    return (uint32_t)__cvta_generic_to_shared(p);
}
__device__ __forceinline__ void mma_bf16(float acc[4], const unsigned a[4],
                                         const unsigned b[2]) {
    asm volatile(
        "mma.sync.aligned.m16n8k16.row.col.f32.bf16.bf16.f32 "
        "{%0,%1,%2,%3}, {%4,%5,%6,%7}, {%8,%9}, {%0,%1,%2,%3};\n"
        : "+f"(acc[0]), "+f"(acc[1]), "+f"(acc[2]), "+f"(acc[3])
        : "r"(a[0]), "r"(a[1]), "r"(a[2]), "r"(a[3]), "r"(b[0]), "r"(b[1]));
}
__device__ __forceinline__ void ldsm_x4(unsigned r[4], unsigned addr) {
    asm volatile("ldmatrix.sync.aligned.m8n8.x4.shared.b16 {%0,%1,%2,%3}, [%4];"
                 : "=r"(r[0]), "=r"(r[1]), "=r"(r[2]), "=r"(r[3]) : "r"(addr));
}
#define CP_A16(saddr, gptr) \
    asm volatile("cp.async.cg.shared.global [%0], [%1], 16;\n" :: "r"(saddr), "l"(gptr))
#define CP_COMMIT() asm volatile("cp.async.commit_group;\n")

// ---------------------------------------------------------------------------
// k0: RoPE tables
// ---------------------------------------------------------------------------
__global__ void rope_table_kernel() {
    int i = blockIdx.x * blockDim.x + threadIdx.x;
    if (i >= S_ * 32) return;
    int s = i >> 5, j = i & 31;
    float invf = __expf(-(float)j * 0.28782313662425586f); // ln(10000)/32
    float ang = (float)s * invf;
    float sv, cv;
    sincosf(ang, &sv, &cv);
    g_sin[i] = sv;
    g_cos[i] = cv;
}

// k1: x fp32 -> bf16
__global__ void cvt_x_kernel(const float4* __restrict__ x) {
    int i = blockIdx.x * blockDim.x + threadIdx.x;
    float4 a = x[2 * i], b = x[2 * i + 1];
    union { __nv_bfloat162 h[4]; uint4 u; } o;
    o.h[0] = __floats2bfloat162_rn(a.x, a.y);
    o.h[1] = __floats2bfloat162_rn(a.z, a.w);
    o.h[2] = __floats2bfloat162_rn(b.x, b.y);
    o.h[3] = __floats2bfloat162_rn(b.z, b.w);
    ((uint4*)g_xb)[i] = o.u;
}

// k2: W (K x N fp32) -> g_wt (N x K bf16)
__global__ void cvt_wt_kernel(const float* __restrict__ W) {
    __shared__ float tile[32][33];
    int nb = blockIdx.x * 32, kb = blockIdx.y * 32;
    int tx = threadIdx.x, ty = threadIdx.y;
#pragma unroll
    for (int u = 0; u < 4; u++)
        tile[ty + u * 8][tx] = W[(size_t)(kb + ty + u * 8) * NCOL + nb + tx];
    __syncthreads();
#pragma unroll
    for (int u = 0; u < 4; u++)
        g_wt[(size_t)(nb + ty + u * 8) * DIN + kb + tx] =
            __float2bfloat16(tile[tx][ty + u * 8]);
}

// ---------------------------------------------------------------------------
// k3: GEMM1  proj = x @ W + b  (8192 x 1536 x 768)
// Block 128x128, BK=64, 3-stage cp.async ring, one sync per k-iter.
// XOR-swizzled 128B smem rows (ldmatrix conflict-free, no padding).
// Fused bias + interleaved RoPE epilogue -> bf16 q/k scratch.
// ---------------------------------------------------------------------------
#define NST 3
#define STGB 16384            // 128 rows x 128 B, per operand per stage
#define KIT  (DIN / 64)       // 12
#define G1_SMEM (NST * 2 * STGB)

__global__ __launch_bounds__(256, 2)
void gemm1_kernel(const float* __restrict__ bias) {
    extern __shared__ __align__(128) char sm1[];
    const uint32_t sbase = cvta_s(sm1);

    const int tid  = threadIdx.x;
    const int lane = tid & 31;
    const int warp = tid >> 5;
    const int wm = (warp & 1) * 64;
    const int wn = (warp >> 1) * 32;
    const int g = lane >> 2;
    const int t = lane & 3;

    const int bm = blockIdx.y * 128;
    const int bn = blockIdx.x * 128;

    // ldmatrix lane geometry
    const int lrow = lane & 15;
    const int lcolB = (lane >> 4) << 4;       // byte offset 0 or 16

#define SW(row, bytecol) ((uint32_t)((row) * 128 + (bytecol)) ^ (uint32_t)(((row) & 7) << 4))

    auto issue = [&](int it) {
        const int st = it % NST;
        const uint32_t sa = sbase + st * STGB;
        const uint32_t sb = sbase + NST * STGB + st * STGB;
        const int k0 = it * 64;
#pragma unroll
        for (int c = 0; c < 4; c++) {
            int idx = tid + c * 256;
            int row = idx >> 3, seg = idx & 7;
            uint32_t sw = SW(row, seg * 16);
            CP_A16(sa + sw, g_xb + (size_t)(bm + row) * DIN + k0 + seg * 8);
            CP_A16(sb + sw, g_wt + (size_t)(bn + row) * DIN + k0 + seg * 8);
        }
        CP_COMMIT();
    };

    float acc[4][4][4] = {};

    issue(0);
    issue(1);

    for (int i = 0; i < KIT; i++) {
        if (i < KIT - 2) asm volatile("cp.async.wait_group 1;" ::: "memory");
        else             asm volatile("cp.async.wait_group 0;" ::: "memory");
        __syncthreads();
        if (i + 2 < KIT) issue(i + 2);

        const int st = i % NST;
        const uint32_t sa = sbase + st * STGB;
        const uint32_t sb = sbase + NST * STGB + st * STGB;
#pragma unroll
        for (int ks = 0; ks < 4; ks++) {
            const int kb = ks * 32;           // byte col of this 16-elem k-chunk
            unsigned afr[4][4], bfr[4][2];
#pragma unroll
            for (int im = 0; im < 4; im++) {
                int r = wm + im * 16 + lrow;
                ldsm_x4(afr[im], sa + SW(r, kb + lcolB));
            }
#pragma unroll
            for (int p = 0; p < 2; p++) {
                int r = wn + p * 16 + lrow;
                unsigned tmp[4];
                ldsm_x4(tmp, sb + SW(r, kb + lcolB));
                bfr[2 * p][0]     = tmp[0];
                bfr[2 * p + 1][0] = tmp[1];
                bfr[2 * p][1]     = tmp[2];
                bfr[2 * p + 1][1] = tmp[3];
            }
#pragma unroll
            for (int im = 0; im < 4; im++)
#pragma unroll
                for (int jn = 0; jn < 4; jn++)
                    mma_bf16(acc[im][jn], afr[im], bfr[jn]);
        }
    }

    // Epilogue: bias + interleaved RoPE -> bf16 q/k scratch (B,OUT,S,HID)
#pragma unroll
    for (int im = 0; im < 4; im++) {
#pragma unroll
        for (int half = 0; half < 2; half++) {
            int m = bm + wm + im * 16 + g + half * 8;
            int b = m >> 9, s = m & 511;
            const float* st_ = g_sin + s * 32;
            const float* ct_ = g_cos + s * 32;
#pragma unroll
            for (int jn = 0; jn < 4; jn++) {
                int c = bn + wn + jn * 8 + 2 * t;   // even
                float v0 = acc[im][jn][half * 2 + 0] + bias[c];
                float v1 = acc[im][jn][half * 2 + 1] + bias[c + 1];
                int o = c >> 7, inner = c & 127, d = inner & 63;
                float ce = ct_[d & 31],       se = st_[d & 31];
                float co = ct_[(d + 1) & 31], so = st_[(d + 1) & 31];
                float r0 = v0 * ce - v1 * se;
                float r1 = v1 * co + v0 * so;
                __nv_bfloat16* dst = ((inner >= 64) ? g_kb : g_qb) +
                    (((size_t)(b * OUT_ + o) * S_ + s) * HID + d);
                *(__nv_bfloat162*)dst = __floats2bfloat162_rn(r0, r1);
            }
        }
    }
#undef SW
}

// ---------------------------------------------------------------------------
// k4: logits = q @ k^T per (b,h); causal tile skip; streaming stores.
// ---------------------------------------------------------------------------
#define G2_LD (HID + 8)

__global__ __launch_bounds__(256, 2)
void gemm2_kernel(const float* __restrict__ mask, float* __restrict__ out) {
    __shared__ __nv_bfloat16 Qs[128][G2_LD];
    __shared__ __nv_bfloat16 Ks[128][G2_LD];

    const int tid  = threadIdx.x;
    const int lane = tid & 31;
    const int warp = tid >> 5;
    const int wm = (warp & 1) * 64;
    const int wn = (warp >> 1) * 32;
    const int g = lane >> 2;
    const int t = lane & 3;

    const int bh  = blockIdx.z;
    const int m0b = blockIdx.y * 128;
    const int n0b = blockIdx.x * 128;
    const int b   = bh / OUT_;

    float acc[4][4][4] = {};

    // Tiles entirely below the diagonal: every element gets -NEG; the
    // GEMM contribution (|v|<~10 against 1e12) is far below rel-err 1e-3.
    const bool skip = (m0b >= n0b + 128);

    if (!skip) {
        const __nv_bfloat16* Qg = g_qb + (size_t)bh * S_ * HID;
        const __nv_bfloat16* Kg = g_kb + (size_t)bh * S_ * HID;
#pragma unroll
        for (int u = 0; u < 4; u++) {
            int vv = tid + u * 256;
            int row = vv >> 3, cb = (vv & 7) * 8;
            *(uint4*)&Qs[row][cb] = *(const uint4*)(Qg + (size_t)(m0b + row) * HID + cb);
            *(uint4*)&Ks[row][cb] = *(const uint4*)(Kg + (size_t)(n0b + row) * HID + cb);
        }
        __syncthreads();

        const int lrow = lane & 15;
        const int lcol = (lane >> 4) << 3;
#pragma unroll
        for (int ks = 0; ks < 4; ks++) {
            const int kb = ks * 16;
            unsigned afr[4][4], bfr[4][2];
#pragma unroll
            for (int im = 0; im < 4; im++)
                ldsm_x4(afr[im], cvta_s(&Qs[wm + im * 16 + lrow][kb + lcol]));
#pragma unroll
            for (int p = 0; p < 2; p++) {
                unsigned tmp[4];
                ldsm_x4(tmp, cvta_s(&Ks[wn + p * 16 + lrow][kb + lcol]));
                bfr[2 * p][0]     = tmp[0];
                bfr[2 * p + 1][0] = tmp[1];
                bfr[2 * p][1]     = tmp[2];
                bfr[2 * p + 1][1] = tmp[3];
            }
#pragma unroll
            for (int im = 0; im < 4; im++)
#pragma unroll
                for (int jn = 0; jn < 4; jn++)
                    mma_bf16(acc[im][jn], afr[im], bfr[jn]);
        }
    }

    // epilogue: mask, strict-lower causal, scale 1/8 (acc=0 on skip path)
    float padv[4][2], png[4][2];
#pragma unroll
    for (int jn = 0; jn < 4; jn++) {
        int n = n0b + wn + jn * 8 + 2 * t;
        float p0 = mask[b * S_ + n], p1 = mask[b * S_ + n + 1];
        padv[jn][0] = p0; padv[jn][1] = p1;
        png[jn][0] = (1.0f - p0) * NEGV;
        png[jn][1] = (1.0f - p1) * NEGV;
    }
#pragma unroll
    for (int im = 0; im < 4; im++) {
#pragma unroll
        for (int half = 0; half < 2; half++) {
            int m = m0b + wm + im * 16 + g + half * 8;
            float* orow = out + ((size_t)bh * S_ + m) * S_;
#pragma unroll
            for (int jn = 0; jn < 4; jn++) {
                int n = n0b + wn + jn * 8 + 2 * t;
                float v0 = acc[im][jn][half * 2 + 0] * padv[jn][0] - png[jn][0];
                float v1 = acc[im][jn][half * 2 + 1] * padv[jn][1] - png[jn][1];
                if (m > n)     v0 -= NEGV;
                if (m > n + 1) v1 -= NEGV;
                __stcs((float2*)(orow + n), make_float2(v0 * 0.125f, v1 * 0.125f));
            }
        }
    }
}

// ---------------------------------------------------------------------------
extern "C" void kernel_launch(void* const* d_in, const int* in_sizes, int n_in,
                              void* d_out, int out_size) {
    const float* x    = (const float*)d_in[0];
    const float* mask = (const float*)d_in[1];
    const float* W    = (const float*)d_in[2];
    const float* bias = (const float*)d_in[3];
    float* out = (float*)d_out;

    static int configured = 0;
    if (!configured) {
        cudaFuncSetAttribute(gemm1_kernel,
                             cudaFuncAttributeMaxDynamicSharedMemorySize, G1_SMEM);
        configured = 1;
    }

    rope_table_kernel<<<(S_ * 32 + 255) / 256, 256>>>();
    cvt_x_kernel<<<(B_ * S_ * DIN / 8 + 255) / 256, 256>>>((const float4*)x);
    cvt_wt_kernel<<<dim3(NCOL / 32, DIN / 32), dim3(32, 8)>>>(W);

    dim3 g1(NCOL / 128, (B_ * S_) / 128);       // (12, 64)
    gemm1_kernel<<<g1, 256, G1_SMEM>>>(bias);

    dim3 g2(S_ / 128, S_ / 128, BH);            // (4, 4, 192)
    gemm2_kernel<<<g2, 256>>>(mask, out);
}